// round 13
// baseline (speedup 1.0000x reference)
#include <cuda_runtime.h>
#include <cuda_bf16.h>
#include <mma.h>
#include <math.h>
#include <cstdint>

using namespace nvcuda;

// Problem constants (GPTBigCode MQA)
#define BB 2
#define SS 2048
#define DD 2048
#define HH 16
#define HDIM 128
#define NQKV (HH * HDIM + 2 * HDIM)   // 2304
#define MM (BB * SS)                  // 4096

// ---------------- scratch (device globals; no allocation allowed) ----------
__device__ __nv_bfloat16 g_qkvhi[MM * NQKV];          // QKV out split [M,2304]
__device__ __nv_bfloat16 g_qkvlo[MM * NQKV];
__device__ __nv_bfloat16 g_Xhi[MM * DD];              // hidden split [M,K]
__device__ __nv_bfloat16 g_Xlo[MM * DD];
__device__ __nv_bfloat16 g_WaThi[NQKV * DD];          // W_attn^T split [N,K]
__device__ __nv_bfloat16 g_WaTlo[NQKV * DD];
__device__ __nv_bfloat16 g_WpThi[DD * DD];            // W_proj^T split [N,K]
__device__ __nv_bfloat16 g_WpTlo[DD * DD];
__device__ __nv_bfloat16 g_AThi[MM * DD];             // attention out split [M,K]
__device__ __nv_bfloat16 g_ATlo[MM * DD];
__device__ __nv_bfloat16 g_Vthi[BB * HDIM * SS];      // V transposed [B][d][s]
__device__ __nv_bfloat16 g_Vtlo[BB * HDIM * SS];

// ---------------- helpers ---------------------------------------------------
__device__ __forceinline__ uint32_t smem_u32(const void* p) {
    uint32_t a;
    asm("{ .reg .u64 t; cvta.to.shared.u64 t, %1; cvt.u32.u64 %0, t; }" : "=r"(a) : "l"(p));
    return a;
}
__device__ __forceinline__ void cp_async16(uint32_t dst, const void* src) {
    asm volatile("cp.async.cg.shared.global [%0], [%1], 16;" :: "r"(dst), "l"(src));
}
__device__ __forceinline__ void cp_commit() {
    asm volatile("cp.async.commit_group;" ::: "memory");
}
template <int N>
__device__ __forceinline__ void cp_wait() {
    asm volatile("cp.async.wait_group %0;" :: "n"(N) : "memory");
}
__device__ __forceinline__ void mma_bf16(float* c, const uint32_t* a,
                                         uint32_t b0, uint32_t b1) {
    asm volatile("mma.sync.aligned.m16n8k16.row.col.f32.bf16.bf16.f32 "
        "{%0,%1,%2,%3}, {%4,%5,%6,%7}, {%8,%9}, {%0,%1,%2,%3};"
        : "+f"(c[0]), "+f"(c[1]), "+f"(c[2]), "+f"(c[3])
        : "r"(a[0]), "r"(a[1]), "r"(a[2]), "r"(a[3]), "r"(b0), "r"(b1));
}
__device__ __forceinline__ void splitf(float v, __nv_bfloat16& h, __nv_bfloat16& l) {
    h = __float2bfloat16(v);
    l = __float2bfloat16(v - __bfloat162float(h));
}
__device__ __forceinline__ uint32_t pack2(float a, float b) {   // a->low, b->high
    uint32_t r;
    asm("cvt.rn.bf16x2.f32 %0, %1, %2;" : "=r"(r) : "f"(b), "f"(a));
    return r;
}

// ---------------------------------------------------------------------------
// split: fp32 -> (bf16 hi, bf16 lo); 4 float4 per thread for MLP=4
// ---------------------------------------------------------------------------
__global__ __launch_bounds__(256) void split_kernel(
    const float* __restrict__ X, __nv_bfloat16* __restrict__ hi,
    __nv_bfloat16* __restrict__ lo, int n)
{
    const int base = blockIdx.x * 4096 + threadIdx.x * 4;
    float4 v[4];
#pragma unroll
    for (int u = 0; u < 4; u++)
        v[u] = *reinterpret_cast<const float4*>(&X[base + u * 1024]);
#pragma unroll
    for (int u = 0; u < 4; u++) {
        const int i = base + u * 1024;
        __nv_bfloat16 h0, h1, h2, h3, l0, l1, l2, l3;
        splitf(v[u].x, h0, l0); splitf(v[u].y, h1, l1);
        splitf(v[u].z, h2, l2); splitf(v[u].w, h3, l3);
        __nv_bfloat162 hp0 = {h0, h1}, hp1 = {h2, h3}, lp0 = {l0, l1}, lp1 = {l2, l3};
        *reinterpret_cast<__nv_bfloat162*>(&hi[i]) = hp0;
        *reinterpret_cast<__nv_bfloat162*>(&hi[i + 2]) = hp1;
        *reinterpret_cast<__nv_bfloat162*>(&lo[i]) = lp0;
        *reinterpret_cast<__nv_bfloat162*>(&lo[i + 2]) = lp1;
    }
}

// ---------------------------------------------------------------------------
// split + transpose: W[K,N] fp32 -> T{hi,lo}[N,K] bf16
// ---------------------------------------------------------------------------
__global__ __launch_bounds__(256) void split_transpose_kernel(
    const float* __restrict__ W, __nv_bfloat16* __restrict__ Thi,
    __nv_bfloat16* __restrict__ Tlo, int K, int N)
{
    __shared__ float t[32][33];
    int tx = threadIdx.x, ty = threadIdx.y;
    int n0 = blockIdx.x * 32, k0 = blockIdx.y * 32;
#pragma unroll
    for (int i = 0; i < 4; i++)
        t[ty + 8 * i][tx] = W[(size_t)(k0 + ty + 8 * i) * N + n0 + tx];
    __syncthreads();
#pragma unroll
    for (int i = 0; i < 4; i++) {
        float v = t[tx][ty + 8 * i];
        __nv_bfloat16 h, l;
        splitf(v, h, l);
        size_t o = (size_t)(n0 + ty + 8 * i) * K + k0 + tx;
        Thi[o] = h;
        Tlo[o] = l;
    }
}

// ---------------------------------------------------------------------------
// wmma bf16 3-term split GEMM + bias (256 threads, warp tile 32x64, 2 CTA/SM).
// Single-sync double-buffered mainloop. SPLIT_OUT: 1/sqrt(HD) on Q cols;
// ntile 17 (V block) writes transposed Vt{hi,lo} directly.
// ---------------------------------------------------------------------------
#define BK 32
#define LDT 40
#define TILE_HB (128 * LDT)
#define TILE_BYTES (TILE_HB * 2)
#define BUF_BYTES (4 * TILE_BYTES)
#define EPI_LD 136

template <bool SPLIT_OUT>
__global__ __launch_bounds__(256, 2)
void wmma_gemm_bias(const __nv_bfloat16* __restrict__ Ahi,
                    const __nv_bfloat16* __restrict__ Alo,
                    const __nv_bfloat16* __restrict__ Bhi,
                    const __nv_bfloat16* __restrict__ Blo,
                    const float* __restrict__ bias, float* __restrict__ C,
                    __nv_bfloat16* __restrict__ Chi, __nv_bfloat16* __restrict__ Clo,
                    __nv_bfloat16* __restrict__ Vthi, __nv_bfloat16* __restrict__ Vtlo,
                    int M, int N, int K)
{
    extern __shared__ char sm[];
    const uint32_t smb = smem_u32(sm);
    const int tid = threadIdx.x;
    const int wid = tid >> 5;
    const int ntile = blockIdx.x, mtile = blockIdx.y;

    const int warp_m = (wid >> 1) * 32;
    const int warp_n = (wid & 1) * 64;

    const __nv_bfloat16* srcs[4] = {
        Ahi + (size_t)mtile * 128 * K, Alo + (size_t)mtile * 128 * K,
        Bhi + (size_t)ntile * 128 * K, Blo + (size_t)ntile * 128 * K };

    auto issue_load = [&](int b, int k0) {
        const uint32_t bufb = smb + b * BUF_BYTES;
#pragma unroll
        for (int t = 0; t < 4; t++) {
            const __nv_bfloat16* s = srcs[t];
            const uint32_t tb = bufb + t * TILE_BYTES;
#pragma unroll
            for (int it = 0; it < 2; it++) {
                int idx = tid + it * 256;
                int row = idx >> 2;
                int ch = idx & 3;
                cp_async16(tb + (row * LDT + ch * 8) * 2,
                           s + (size_t)row * K + k0 + ch * 8);
            }
        }
        cp_commit();
    };

    wmma::fragment<wmma::accumulator, 16, 16, 16, float> acc[2][4];
#pragma unroll
    for (int i = 0; i < 2; i++)
#pragma unroll
        for (int j = 0; j < 4; j++) wmma::fill_fragment(acc[i][j], 0.0f);

    const int niter = K / BK;
    issue_load(0, 0);

    for (int iter = 0; iter < niter; iter++) {
        const int buf = iter & 1;
        cp_wait<0>();           // load(iter) complete
        __syncthreads();        // all threads done with buf^1 compute & see data
        if (iter + 1 < niter)
            issue_load(buf ^ 1, (iter + 1) * BK);   // overlaps compute below

        const __nv_bfloat16* base = reinterpret_cast<const __nv_bfloat16*>(sm + buf * BUF_BYTES);
        const __nv_bfloat16* As_hi = base;
        const __nv_bfloat16* As_lo = base + TILE_HB;
        const __nv_bfloat16* Bs_hi = base + 2 * TILE_HB;
        const __nv_bfloat16* Bs_lo = base + 3 * TILE_HB;

#pragma unroll
        for (int kk = 0; kk < BK; kk += 16) {
            wmma::fragment<wmma::matrix_a, 16, 16, 16, __nv_bfloat16, wmma::row_major> ah[2], al[2];
#pragma unroll
            for (int i = 0; i < 2; i++) {
                wmma::load_matrix_sync(ah[i], As_hi + (warp_m + 16 * i) * LDT + kk, LDT);
                wmma::load_matrix_sync(al[i], As_lo + (warp_m + 16 * i) * LDT + kk, LDT);
            }
#pragma unroll
            for (int j = 0; j < 4; j++) {
                wmma::fragment<wmma::matrix_b, 16, 16, 16, __nv_bfloat16, wmma::col_major> bh, bl;
                wmma::load_matrix_sync(bh, Bs_hi + (warp_n + 16 * j) * LDT + kk, LDT);
                wmma::load_matrix_sync(bl, Bs_lo + (warp_n + 16 * j) * LDT + kk, LDT);
#pragma unroll
                for (int i = 0; i < 2; i++) {
                    wmma::mma_sync(acc[i][j], ah[i], bh, acc[i][j]);
                    wmma::mma_sync(acc[i][j], ah[i], bl, acc[i][j]);
                    wmma::mma_sync(acc[i][j], al[i], bh, acc[i][j]);
                }
            }
        }
    }
    __syncthreads();   // before epilogue reuses smem

    float* Cs = reinterpret_cast<float*>(sm);
#pragma unroll
    for (int i = 0; i < 2; i++)
#pragma unroll
        for (int j = 0; j < 4; j++)
            wmma::store_matrix_sync(Cs + (warp_m + 16 * i) * EPI_LD + warp_n + 16 * j,
                                    acc[i][j], EPI_LD, wmma::mem_row_major);
    __syncthreads();

    if (SPLIT_OUT && ntile == 17) {
        // V block: write transposed Vt[b][d][s] split bf16 (skip qkv store)
        const int b2 = mtile >> 4;                // batch
        const int s0 = (mtile & 15) * 128;        // seq offset
#pragma unroll
        for (int it = 0; it < 32; it++) {
            int idx = tid + it * 256;             // 0..8191
            int d = idx >> 6;                     // 0..127
            int sp = idx & 63;                    // s-pair index
            float bconst = bias[2176 + d];
            float v0 = Cs[(2 * sp) * EPI_LD + d] + bconst;
            float v1 = Cs[(2 * sp + 1) * EPI_LD + d] + bconst;
            __nv_bfloat16 h0, l0, h1, l1;
            splitf(v0, h0, l0); splitf(v1, h1, l1);
            __nv_bfloat162 hp = {h0, h1}, lp = {l0, l1};
            size_t o = (size_t)(b2 * HDIM + d) * SS + s0 + 2 * sp;
            *reinterpret_cast<__nv_bfloat162*>(&Vthi[o]) = hp;
            *reinterpret_cast<__nv_bfloat162*>(&Vtlo[o]) = lp;
        }
        return;
    }

    // Q-column scale (QKV GEMM only): cols < H*HD get 1/sqrt(HD), post-bias.
    const float qs = (SPLIT_OUT && ntile < (HH * HDIM) / 128)
                     ? 0.08838834764831845f : 1.0f;

#pragma unroll
    for (int it = 0; it < 16; it++) {
        int idx = tid + it * 256;
        int row = idx >> 5;
        int c4 = (idx & 31) * 4;
        float4 v = *reinterpret_cast<const float4*>(&Cs[row * EPI_LD + c4]);
        const int col0 = ntile * 128 + c4;
        v.x += bias[col0 + 0];
        v.y += bias[col0 + 1];
        v.z += bias[col0 + 2];
        v.w += bias[col0 + 3];
        const size_t o = (size_t)(mtile * 128 + row) * N + col0;
        if (SPLIT_OUT) {
            v.x *= qs; v.y *= qs; v.z *= qs; v.w *= qs;
            __nv_bfloat16 h0, h1, h2, h3, l0, l1, l2, l3;
            splitf(v.x, h0, l0); splitf(v.y, h1, l1);
            splitf(v.z, h2, l2); splitf(v.w, h3, l3);
            __nv_bfloat162 hp0 = {h0, h1}, hp1 = {h2, h3};
            __nv_bfloat162 lp0 = {l0, l1}, lp1 = {l2, l3};
            *reinterpret_cast<__nv_bfloat162*>(&Chi[o]) = hp0;
            *reinterpret_cast<__nv_bfloat162*>(&Chi[o + 2]) = hp1;
            *reinterpret_cast<__nv_bfloat162*>(&Clo[o]) = lp0;
            *reinterpret_cast<__nv_bfloat162*>(&Clo[o + 2]) = lp1;
        } else {
            *reinterpret_cast<float4*>(&C[o]) = v;
        }
    }
}

// ---------------------------------------------------------------------------
// MQA flash attention v6 (round-11 proven, 3-term everywhere) — mma m16n8k16,
// pre-scaled Q, peeled diagonal tile, branch-free mainloop, cp.async ping-pong.
// ---------------------------------------------------------------------------
#define ALD 136
#define ATILE (128 * ALD)

__global__ __launch_bounds__(256, 1) void mqa_attn_v6(
    const __nv_bfloat16* __restrict__ qhi, const __nv_bfloat16* __restrict__ qlo,
    const __nv_bfloat16* __restrict__ vthi, const __nv_bfloat16* __restrict__ vtlo,
    __nv_bfloat16* __restrict__ ohi, __nv_bfloat16* __restrict__ olo)
{
    extern __shared__ __nv_bfloat16 smh[];
    __nv_bfloat16* Qhi = smh;
    __nv_bfloat16* Qlo = smh + ATILE;
    __nv_bfloat16* Khi = smh + 2 * ATILE;
    __nv_bfloat16* Klo = smh + 3 * ATILE;
    __nv_bfloat16* Vhi = smh + 4 * ATILE;
    __nv_bfloat16* Vlo = smh + 5 * ATILE;
    const uint32_t smb = smem_u32(smh);
    const uint32_t oQhi = 0, oQlo = ATILE * 2, oKhi = 2 * ATILE * 2,
                   oKlo = 3 * ATILE * 2, oVhi = 4 * ATILE * 2, oVlo = 5 * ATILE * 2;

    const int tid = threadIdx.x;
    const int w = tid >> 5;
    const int lane = tid & 31;
    const int g = lane >> 2;
    const int t = lane & 3;
    const int b = blockIdx.y;
    const int q0 = (gridDim.x - 1 - blockIdx.x) * 8;   // heaviest first

    const int r_lo = w * 16 + g;

    // ---- async load Q (pre-scaled by QKV epilogue) ----
#pragma unroll
    for (int it = 0; it < 8; ++it) {
        int idx = tid + it * 256;
        int row = idx >> 4;
        int ch = idx & 15;
        size_t src = (size_t)(b * SS + q0 + (row & 7)) * NQKV + (row >> 3) * HDIM + ch * 8;
        uint32_t d = (uint32_t)(row * ALD + ch * 8) * 2;
        cp_async16(smb + oQhi + d, qhi + src);
        cp_async16(smb + oQlo + d, qlo + src);
    }
    // ---- async load K(0) ----
#pragma unroll
    for (int it = 0; it < 8; ++it) {
        int idx = tid + it * 256;
        int row = idx >> 4;
        int ch = idx & 15;
        size_t src = (size_t)(b * SS + row) * NQKV + HH * HDIM + ch * 8;
        uint32_t d = (uint32_t)(row * ALD + ch * 8) * 2;
        cp_async16(smb + oKhi + d, qhi + src);
        cp_async16(smb + oKlo + d, qlo + src);
    }
    cp_commit();

    float m0 = -INFINITY, m1 = -INFINITY, l0s = 0.0f, l1s = 0.0f;
    float O[16][4];
#pragma unroll
    for (int j = 0; j < 16; j++)
#pragma unroll
        for (int c = 0; c < 4; c++) O[j][c] = 0.0f;

    const int ntiles = (q0 + 7) / 128 + 1;

    auto softmax_update = [&](float s[16][4]) {
        float mx0 = -INFINITY, mx1 = -INFINITY;
#pragma unroll
        for (int j = 0; j < 16; ++j) {
            mx0 = fmaxf(mx0, fmaxf(s[j][0], s[j][1]));
            mx1 = fmaxf(mx1, fmaxf(s[j][2], s[j][3]));
        }
        mx0 = fmaxf(mx0, __shfl_xor_sync(0xffffffffu, mx0, 1));
        mx0 = fmaxf(mx0, __shfl_xor_sync(0xffffffffu, mx0, 2));
        mx1 = fmaxf(mx1, __shfl_xor_sync(0xffffffffu, mx1, 1));
        mx1 = fmaxf(mx1, __shfl_xor_sync(0xffffffffu, mx1, 2));
        const float mn0 = fmaxf(m0, mx0), mn1 = fmaxf(m1, mx1);
        const float corr0 = __expf(m0 - mn0), corr1 = __expf(m1 - mn1);
        m0 = mn0; m1 = mn1;

        float sum0 = 0.0f, sum1 = 0.0f;
#pragma unroll
        for (int j = 0; j < 16; ++j) {
            s[j][0] = __expf(s[j][0] - mn0);
            s[j][1] = __expf(s[j][1] - mn0);
            s[j][2] = __expf(s[j][2] - mn1);
            s[j][3] = __expf(s[j][3] - mn1);
            sum0 += s[j][0] + s[j][1];
            sum1 += s[j][2] + s[j][3];
        }
        sum0 += __shfl_xor_sync(0xffffffffu, sum0, 1);
        sum0 += __shfl_xor_sync(0xffffffffu, sum0, 2);
        sum1 += __shfl_xor_sync(0xffffffffu, sum1, 1);
        sum1 += __shfl_xor_sync(0xffffffffu, sum1, 2);
        l0s = l0s * corr0 + sum0;
        l1s = l1s * corr1 + sum1;

#pragma unroll
        for (int j = 0; j < 16; ++j) {
            O[j][0] *= corr0; O[j][1] *= corr0;
            O[j][2] *= corr1; O[j][3] *= corr1;
        }
    };

    auto repack = [&](const float s[16][4], uint32_t pah[8][4], uint32_t pal[8][4]) {
#pragma unroll
        for (int ss = 0; ss < 8; ++ss) {
            __nv_bfloat16 h, l;
            float h00, q00, h01, q01, h10, q10, h11, q11;
            float h20, q20, h21, q21, h30, q30, h31, q31;
            splitf(s[2 * ss][0], h, l); h00 = __bfloat162float(h); q00 = __bfloat162float(l);
            splitf(s[2 * ss][1], h, l); h01 = __bfloat162float(h); q01 = __bfloat162float(l);
            splitf(s[2 * ss][2], h, l); h10 = __bfloat162float(h); q10 = __bfloat162float(l);
            splitf(s[2 * ss][3], h, l); h11 = __bfloat162float(h); q11 = __bfloat162float(l);
            splitf(s[2 * ss + 1][0], h, l); h20 = __bfloat162float(h); q20 = __bfloat162float(l);
            splitf(s[2 * ss + 1][1], h, l); h21 = __bfloat162float(h); q21 = __bfloat162float(l);
            splitf(s[2 * ss + 1][2], h, l); h30 = __bfloat162float(h); q30 = __bfloat162float(l);
            splitf(s[2 * ss + 1][3], h, l); h31 = __bfloat162float(h); q31 = __bfloat162float(l);
            pah[ss][0] = pack2(h00, h01); pal[ss][0] = pack2(q00, q01);
            pah[ss][1] = pack2(h10, h11); pal[ss][1] = pack2(q10, q11);
            pah[ss][2] = pack2(h20, h21); pal[ss][2] = pack2(q20, q21);
            pah[ss][3] = pack2(h30, h31); pal[ss][3] = pack2(q30, q31);
        }
    };

    auto issue_V = [&](int t0) {
#pragma unroll
        for (int it = 0; it < 8; ++it) {
            int idx = tid + it * 256;
            int row = idx >> 4;
            int ch = idx & 15;
            size_t src = (size_t)(b * HDIM + row) * SS + t0 + ch * 8;
            uint32_t d = (uint32_t)(row * ALD + ch * 8) * 2;
            cp_async16(smb + oVhi + d, vthi + src);
            cp_async16(smb + oVlo + d, vtlo + src);
        }
        cp_commit();
    };

    auto load_Qfrag = [&](int k, uint32_t ah[4], uint32_t al[4]) {
        const int d0 = 16 * k + 2 * t;
        ah[0] = *reinterpret_cast<const uint32_t*>(&Qhi[r_lo * ALD + d0]);
        ah[1] = *reinterpret_cast<const uint32_t*>(&Qhi[(r_lo + 8) * ALD + d0]);
        ah[2] = *reinterpret_cast<const uint32_t*>(&Qhi[r_lo * ALD + d0 + 8]);
        ah[3] = *reinterpret_cast<const uint32_t*>(&Qhi[(r_lo + 8) * ALD + d0 + 8]);
        al[0] = *reinterpret_cast<const uint32_t*>(&Qlo[r_lo * ALD + d0]);
        al[1] = *reinterpret_cast<const uint32_t*>(&Qlo[(r_lo + 8) * ALD + d0]);
        al[2] = *reinterpret_cast<const uint32_t*>(&Qlo[r_lo * ALD + d0 + 8]);
        al[3] = *reinterpret_cast<const uint32_t*>(&Qlo[(r_lo + 8) * ALD + d0 + 8]);
    };

    cp_wait<0>();
    __syncthreads();

    // ================= mainloop: full tiles, branch-free =================
    for (int tt = 0; tt < ntiles - 1; ++tt) {
        const int t0 = tt * 128;

        issue_V(t0);

        float s[16][4];
#pragma unroll
        for (int j = 0; j < 16; j++)
#pragma unroll
            for (int c = 0; c < 4; c++) s[j][c] = 0.0f;

#pragma unroll
        for (int k = 0; k < 8; ++k) {
            uint32_t ah[4], al[4];
            load_Qfrag(k, ah, al);
            const int d0 = 16 * k + 2 * t;
#pragma unroll
            for (int j = 0; j < 16; ++j) {
                const int kr = (8 * j + g) * ALD + d0;
                uint32_t bh0 = *reinterpret_cast<const uint32_t*>(&Khi[kr]);
                uint32_t bh1 = *reinterpret_cast<const uint32_t*>(&Khi[kr + 8]);
                uint32_t bl0 = *reinterpret_cast<const uint32_t*>(&Klo[kr]);
                uint32_t bl1 = *reinterpret_cast<const uint32_t*>(&Klo[kr + 8]);
                mma_bf16(s[j], ah, bh0, bh1);
                mma_bf16(s[j], ah, bl0, bl1);
                mma_bf16(s[j], al, bh0, bh1);
            }
        }

        cp_wait<0>();
        __syncthreads();

        softmax_update(s);

        uint32_t pah[8][4], pal[8][4];
        repack(s, pah, pal);

        // issue K(tt+1)
        {
            const int t1 = t0 + 128;
#pragma unroll
            for (int it = 0; it < 8; ++it) {
                int idx = tid + it * 256;
                int row = idx >> 4;
                int ch = idx & 15;
                size_t src = (size_t)(b * SS + t1 + row) * NQKV + HH * HDIM + ch * 8;
                uint32_t d = (uint32_t)(row * ALD + ch * 8) * 2;
                cp_async16(smb + oKhi + d, qhi + src);
                cp_async16(smb + oKlo + d, qlo + src);
            }
            cp_commit();
        }

        // PV, branch-free
#pragma unroll
        for (int ss = 0; ss < 8; ++ss) {
            const int kb = 16 * ss + 2 * t;
#pragma unroll
            for (int j2 = 0; j2 < 16; ++j2) {
                const int vr = (8 * j2 + g) * ALD + kb;
                uint32_t bh0 = *reinterpret_cast<const uint32_t*>(&Vhi[vr]);
                uint32_t bh1 = *reinterpret_cast<const uint32_t*>(&Vhi[vr + 8]);
                uint32_t bl0 = *reinterpret_cast<const uint32_t*>(&Vlo[vr]);
                uint32_t bl1 = *reinterpret_cast<const uint32_t*>(&Vlo[vr + 8]);
                mma_bf16(O[j2], pah[ss], bh0, bh1);
                mma_bf16(O[j2], pah[ss], bl0, bl1);
                mma_bf16(O[j2], pal[ss], bh0, bh1);
            }
        }

        cp_wait<0>();
        __syncthreads();
    }

    // ================= peeled diagonal tile =================
    {
        const int t0 = (ntiles - 1) * 128;
        const int nvalid = q0 + 8 - t0;
        const int njfrag = (nvalid + 7) >> 3;
        const int nsfrag = (nvalid + 15) >> 4;

        issue_V(t0);

        float s[16][4];
#pragma unroll
        for (int j = 0; j < 16; j++)
#pragma unroll
            for (int c = 0; c < 4; c++) s[j][c] = 0.0f;

#pragma unroll
        for (int k = 0; k < 8; ++k) {
            uint32_t ah[4], al[4];
            load_Qfrag(k, ah, al);
            const int d0 = 16 * k + 2 * t;
            for (int j = 0; j < njfrag; ++j) {
                const int kr = (8 * j + g) * ALD + d0;
                uint32_t bh0 = *reinterpret_cast<const uint32_t*>(&Khi[kr]);
                uint32_t bh1 = *reinterpret_cast<const uint32_t*>(&Khi[kr + 8]);
                uint32_t bl0 = *reinterpret_cast<const uint32_t*>(&Klo[kr]);
                uint32_t bl1 = *reinterpret_cast<const uint32_t*>(&Klo[kr + 8]);
                mma_bf16(s[j], ah, bh0, bh1);
                mma_bf16(s[j], ah, bl0, bl1);
                mma_bf16(s[j], al, bh0, bh1);
            }
        }

        cp_wait<0>();
        __syncthreads();

#pragma unroll
        for (int j = 0; j < 16; ++j) {
            const int col = t0 + 8 * j + 2 * t;
            if (col > q0 + g)     { s[j][0] = -1e30f; s[j][2] = -1e30f; }
            if (col + 1 > q0 + g) { s[j][1] = -1e30f; s[j][3] = -1e30f; }
        }

        softmax_update(s);

        uint32_t pah[8][4], pal[8][4];
        repack(s, pah, pal);

        for (int ss = 0; ss < nsfrag; ++ss) {
            const int kb = 16 * ss + 2 * t;
#pragma unroll
            for (int j2 = 0; j2 < 16; ++j2) {
                const int vr = (8 * j2 + g) * ALD + kb;
                uint32_t bh0 = *reinterpret_cast<const uint32_t*>(&Vhi[vr]);
                uint32_t bh1 = *reinterpret_cast<const uint32_t*>(&Vhi[vr + 8]);
                uint32_t bl0 = *reinterpret_cast<const uint32_t*>(&Vlo[vr]);
                uint32_t bl1 = *reinterpret_cast<const uint32_t*>(&Vlo[vr + 8]);
                mma_bf16(O[j2], pah[ss], bh0, bh1);
                mma_bf16(O[j2], pah[ss], bl0, bl1);
                mma_bf16(O[j2], pal[ss], bh0, bh1);
            }
        }
    }

    // ---- epilogue: normalize + split-store bf16 hi/lo ----
    const float inv0 = 1.0f / l0s, inv1 = 1.0f / l1s;
    const size_t row0 = (size_t)(b * SS + q0 + g) * DD;
    const int h_lo = 2 * w, h_hi = 2 * w + 1;
#pragma unroll
    for (int j2 = 0; j2 < 16; ++j2) {
        const int d = 8 * j2 + 2 * t;
        float v00 = O[j2][0] * inv0, v01 = O[j2][1] * inv0;
        float v10 = O[j2][2] * inv1, v11 = O[j2][3] * inv1;
        __nv_bfloat16 h0, l0, h1, l1;
        splitf(v00, h0, l0); splitf(v01, h1, l1);
        __nv_bfloat162 hp = {h0, h1}, lp = {l0, l1};
        *reinterpret_cast<__nv_bfloat162*>(&ohi[row0 + h_lo * HDIM + d]) = hp;
        *reinterpret_cast<__nv_bfloat162*>(&olo[row0 + h_lo * HDIM + d]) = lp;
        splitf(v10, h0, l0); splitf(v11, h1, l1);
        __nv_bfloat162 hp2 = {h0, h1}, lp2 = {l0, l1};
        *reinterpret_cast<__nv_bfloat162*>(&ohi[row0 + h_hi * HDIM + d]) = hp2;
        *reinterpret_cast<__nv_bfloat162*>(&olo[row0 + h_hi * HDIM + d]) = lp2;
    }
}

// ---------------------------------------------------------------------------
extern "C" void kernel_launch(void* const* d_in, const int* in_sizes, int n_in,
                              void* d_out, int out_size)
{
    const float* hidden = (const float*)d_in[0];
    const float* W_attn = (const float*)d_in[1];
    const float* b_attn = (const float*)d_in[2];
    const float* W_proj = (const float*)d_in[3];
    const float* b_proj = (const float*)d_in[4];
    float* out = (float*)d_out;

    __nv_bfloat16 *qkvhi, *qkvlo, *Xhi, *Xlo, *WaThi, *WaTlo, *WpThi, *WpTlo;
    __nv_bfloat16 *AThi, *ATlo, *Vthi, *Vtlo;
    cudaGetSymbolAddress((void**)&qkvhi, g_qkvhi);
    cudaGetSymbolAddress((void**)&qkvlo, g_qkvlo);
    cudaGetSymbolAddress((void**)&Xhi, g_Xhi);
    cudaGetSymbolAddress((void**)&Xlo, g_Xlo);
    cudaGetSymbolAddress((void**)&WaThi, g_WaThi);
    cudaGetSymbolAddress((void**)&WaTlo, g_WaTlo);
    cudaGetSymbolAddress((void**)&WpThi, g_WpThi);
    cudaGetSymbolAddress((void**)&WpTlo, g_WpTlo);
    cudaGetSymbolAddress((void**)&AThi, g_AThi);
    cudaGetSymbolAddress((void**)&ATlo, g_ATlo);
    cudaGetSymbolAddress((void**)&Vthi, g_Vthi);
    cudaGetSymbolAddress((void**)&Vtlo, g_Vtlo);

    const int attn_smem = 6 * ATILE * sizeof(__nv_bfloat16);      // 208,896 B
    const int gemm_smem = 2 * BUF_BYTES;                          // 81,920 B
    cudaFuncSetAttribute(mqa_attn_v6,
                         cudaFuncAttributeMaxDynamicSharedMemorySize, attn_smem);
    cudaFuncSetAttribute(wmma_gemm_bias<true>,
                         cudaFuncAttributeMaxDynamicSharedMemorySize, gemm_smem);
    cudaFuncSetAttribute(wmma_gemm_bias<false>,
                         cudaFuncAttributeMaxDynamicSharedMemorySize, gemm_smem);

    // 0) input splits
    split_kernel<<<MM * DD / 4096, 256>>>(hidden, Xhi, Xlo, MM * DD);
    {
        dim3 g(NQKV / 32, DD / 32), blk(32, 8);
        split_transpose_kernel<<<g, blk>>>(W_attn, WaThi, WaTlo, DD, NQKV);
    }
    {
        dim3 g(DD / 32, DD / 32), blk(32, 8);
        split_transpose_kernel<<<g, blk>>>(W_proj, WpThi, WpTlo, DD, DD);
    }

    // 1) QKV GEMM -> split bf16 output (Q pre-scaled; V written transposed)
    {
        dim3 grid(NQKV / 128, MM / 128);
        wmma_gemm_bias<true><<<grid, 256, gemm_smem>>>(
            Xhi, Xlo, WaThi, WaTlo, b_attn, nullptr, qkvhi, qkvlo,
            Vthi, Vtlo, MM, NQKV, DD);
    }

    // 2) MQA causal flash attention -> split bf16 output
    {
        dim3 grid(SS / 8, BB);
        mqa_attn_v6<<<grid, 256, attn_smem>>>(qkvhi, qkvlo, Vthi, Vtlo, AThi, ATlo);
    }

    // 3) Projection GEMM -> f32 final output
    {
        dim3 grid(DD / 128, MM / 128);
        wmma_gemm_bias<false><<<grid, 256, gemm_smem>>>(
            AThi, ATlo, WpThi, WpTlo, b_proj, out, nullptr, nullptr,
            nullptr, nullptr, MM, DD, DD);
    }
}

// round 14
// speedup vs baseline: 1.0394x; 1.0394x over previous
#include <cuda_runtime.h>
#include <cuda_bf16.h>
#include <mma.h>
#include <math.h>
#include <cstdint>

using namespace nvcuda;

// Problem constants (GPTBigCode MQA)
#define BB 2
#define SS 2048
#define DD 2048
#define HH 16
#define HDIM 128
#define NQKV (HH * HDIM + 2 * HDIM)   // 2304
#define MM (BB * SS)                  // 4096

// ---------------- scratch (device globals; no allocation allowed) ----------
__device__ __nv_bfloat16 g_qkvhi[MM * NQKV];          // QKV out split [M,2304]
__device__ __nv_bfloat16 g_qkvlo[MM * NQKV];
__device__ __nv_bfloat16 g_Xhi[MM * DD];              // hidden split [M,K]
__device__ __nv_bfloat16 g_Xlo[MM * DD];
__device__ __nv_bfloat16 g_WaThi[NQKV * DD];          // W_attn^T split [N,K]
__device__ __nv_bfloat16 g_WaTlo[NQKV * DD];
__device__ __nv_bfloat16 g_WpThi[DD * DD];            // W_proj^T split [N,K]
__device__ __nv_bfloat16 g_WpTlo[DD * DD];
__device__ __nv_bfloat16 g_AThi[MM * DD];             // attention out split [M,K]
__device__ __nv_bfloat16 g_ATlo[MM * DD];
__device__ __nv_bfloat16 g_Vthi[BB * HDIM * SS];      // V transposed [B][d][s]
__device__ __nv_bfloat16 g_Vtlo[BB * HDIM * SS];

// ---------------- helpers ---------------------------------------------------
__device__ __forceinline__ uint32_t smem_u32(const void* p) {
    uint32_t a;
    asm("{ .reg .u64 t; cvta.to.shared.u64 t, %1; cvt.u32.u64 %0, t; }" : "=r"(a) : "l"(p));
    return a;
}
__device__ __forceinline__ void cp_async16(uint32_t dst, const void* src) {
    asm volatile("cp.async.cg.shared.global [%0], [%1], 16;" :: "r"(dst), "l"(src));
}
__device__ __forceinline__ void cp_commit() {
    asm volatile("cp.async.commit_group;" ::: "memory");
}
template <int N>
__device__ __forceinline__ void cp_wait() {
    asm volatile("cp.async.wait_group %0;" :: "n"(N) : "memory");
}
__device__ __forceinline__ void mma_bf16(float* c, const uint32_t* a,
                                         uint32_t b0, uint32_t b1) {
    asm volatile("mma.sync.aligned.m16n8k16.row.col.f32.bf16.bf16.f32 "
        "{%0,%1,%2,%3}, {%4,%5,%6,%7}, {%8,%9}, {%0,%1,%2,%3};"
        : "+f"(c[0]), "+f"(c[1]), "+f"(c[2]), "+f"(c[3])
        : "r"(a[0]), "r"(a[1]), "r"(a[2]), "r"(a[3]), "r"(b0), "r"(b1));
}
__device__ __forceinline__ void splitf(float v, __nv_bfloat16& h, __nv_bfloat16& l) {
    h = __float2bfloat16(v);
    l = __float2bfloat16(v - __bfloat162float(h));
}
__device__ __forceinline__ uint32_t pack2(float a, float b) {   // a->low, b->high
    uint32_t r;
    asm("cvt.rn.bf16x2.f32 %0, %1, %2;" : "=r"(r) : "f"(b), "f"(a));
    return r;
}

// ---------------------------------------------------------------------------
// split: fp32 -> (bf16 hi, bf16 lo); 4 float4 per thread for MLP=4
// ---------------------------------------------------------------------------
__global__ __launch_bounds__(256) void split_kernel(
    const float* __restrict__ X, __nv_bfloat16* __restrict__ hi,
    __nv_bfloat16* __restrict__ lo, int n)
{
    const int base = blockIdx.x * 4096 + threadIdx.x * 4;
    float4 v[4];
#pragma unroll
    for (int u = 0; u < 4; u++)
        v[u] = *reinterpret_cast<const float4*>(&X[base + u * 1024]);
#pragma unroll
    for (int u = 0; u < 4; u++) {
        const int i = base + u * 1024;
        __nv_bfloat16 h0, h1, h2, h3, l0, l1, l2, l3;
        splitf(v[u].x, h0, l0); splitf(v[u].y, h1, l1);
        splitf(v[u].z, h2, l2); splitf(v[u].w, h3, l3);
        __nv_bfloat162 hp0 = {h0, h1}, hp1 = {h2, h3}, lp0 = {l0, l1}, lp1 = {l2, l3};
        *reinterpret_cast<__nv_bfloat162*>(&hi[i]) = hp0;
        *reinterpret_cast<__nv_bfloat162*>(&hi[i + 2]) = hp1;
        *reinterpret_cast<__nv_bfloat162*>(&lo[i]) = lp0;
        *reinterpret_cast<__nv_bfloat162*>(&lo[i + 2]) = lp1;
    }
}

// ---------------------------------------------------------------------------
// split + transpose: W[K,N] fp32 -> T{hi,lo}[N,K] bf16
// ---------------------------------------------------------------------------
__global__ __launch_bounds__(256) void split_transpose_kernel(
    const float* __restrict__ W, __nv_bfloat16* __restrict__ Thi,
    __nv_bfloat16* __restrict__ Tlo, int K, int N)
{
    __shared__ float t[32][33];
    int tx = threadIdx.x, ty = threadIdx.y;
    int n0 = blockIdx.x * 32, k0 = blockIdx.y * 32;
#pragma unroll
    for (int i = 0; i < 4; i++)
        t[ty + 8 * i][tx] = W[(size_t)(k0 + ty + 8 * i) * N + n0 + tx];
    __syncthreads();
#pragma unroll
    for (int i = 0; i < 4; i++) {
        float v = t[tx][ty + 8 * i];
        __nv_bfloat16 h, l;
        splitf(v, h, l);
        size_t o = (size_t)(n0 + ty + 8 * i) * K + k0 + tx;
        Thi[o] = h;
        Tlo[o] = l;
    }
}

// ---------------------------------------------------------------------------
// wmma bf16 3-term split GEMM + bias (256 threads, warp tile 32x64, 2 CTA/SM).
// Round-11 proven mainloop (issue-before-wait, cp_wait<1>, two syncs).
// SPLIT_OUT: 1/sqrt(HD) on Q cols; ntile 17 (V block) writes transposed
// Vt{hi,lo} directly.
// ---------------------------------------------------------------------------
#define BK 32
#define LDT 40
#define TILE_HB (128 * LDT)
#define TILE_BYTES (TILE_HB * 2)
#define BUF_BYTES (4 * TILE_BYTES)
#define EPI_LD 136

template <bool SPLIT_OUT>
__global__ __launch_bounds__(256, 2)
void wmma_gemm_bias(const __nv_bfloat16* __restrict__ Ahi,
                    const __nv_bfloat16* __restrict__ Alo,
                    const __nv_bfloat16* __restrict__ Bhi,
                    const __nv_bfloat16* __restrict__ Blo,
                    const float* __restrict__ bias, float* __restrict__ C,
                    __nv_bfloat16* __restrict__ Chi, __nv_bfloat16* __restrict__ Clo,
                    __nv_bfloat16* __restrict__ Vthi, __nv_bfloat16* __restrict__ Vtlo,
                    int M, int N, int K)
{
    extern __shared__ char sm[];
    const uint32_t smb = smem_u32(sm);
    const int tid = threadIdx.x;
    const int wid = tid >> 5;
    const int ntile = blockIdx.x, mtile = blockIdx.y;

    const int warp_m = (wid >> 1) * 32;
    const int warp_n = (wid & 1) * 64;

    const __nv_bfloat16* srcs[4] = {
        Ahi + (size_t)mtile * 128 * K, Alo + (size_t)mtile * 128 * K,
        Bhi + (size_t)ntile * 128 * K, Blo + (size_t)ntile * 128 * K };

    auto issue_load = [&](int b, int k0) {
        const uint32_t bufb = smb + b * BUF_BYTES;
#pragma unroll
        for (int t = 0; t < 4; t++) {
            const __nv_bfloat16* s = srcs[t];
            const uint32_t tb = bufb + t * TILE_BYTES;
#pragma unroll
            for (int it = 0; it < 2; it++) {
                int idx = tid + it * 256;
                int row = idx >> 2;
                int ch = idx & 3;
                cp_async16(tb + (row * LDT + ch * 8) * 2,
                           s + (size_t)row * K + k0 + ch * 8);
            }
        }
        cp_commit();
    };

    wmma::fragment<wmma::accumulator, 16, 16, 16, float> acc[2][4];
#pragma unroll
    for (int i = 0; i < 2; i++)
#pragma unroll
        for (int j = 0; j < 4; j++) wmma::fill_fragment(acc[i][j], 0.0f);

    const int niter = K / BK;
    issue_load(0, 0);

    for (int iter = 0; iter < niter; iter++) {
        const int buf = iter & 1;
        if (iter + 1 < niter) {
            issue_load(buf ^ 1, (iter + 1) * BK);
            cp_wait<1>();
        } else {
            cp_wait<0>();
        }
        __syncthreads();

        const __nv_bfloat16* base = reinterpret_cast<const __nv_bfloat16*>(sm + buf * BUF_BYTES);
        const __nv_bfloat16* As_hi = base;
        const __nv_bfloat16* As_lo = base + TILE_HB;
        const __nv_bfloat16* Bs_hi = base + 2 * TILE_HB;
        const __nv_bfloat16* Bs_lo = base + 3 * TILE_HB;

#pragma unroll
        for (int kk = 0; kk < BK; kk += 16) {
            wmma::fragment<wmma::matrix_a, 16, 16, 16, __nv_bfloat16, wmma::row_major> ah[2], al[2];
#pragma unroll
            for (int i = 0; i < 2; i++) {
                wmma::load_matrix_sync(ah[i], As_hi + (warp_m + 16 * i) * LDT + kk, LDT);
                wmma::load_matrix_sync(al[i], As_lo + (warp_m + 16 * i) * LDT + kk, LDT);
            }
#pragma unroll
            for (int j = 0; j < 4; j++) {
                wmma::fragment<wmma::matrix_b, 16, 16, 16, __nv_bfloat16, wmma::col_major> bh, bl;
                wmma::load_matrix_sync(bh, Bs_hi + (warp_n + 16 * j) * LDT + kk, LDT);
                wmma::load_matrix_sync(bl, Bs_lo + (warp_n + 16 * j) * LDT + kk, LDT);
#pragma unroll
                for (int i = 0; i < 2; i++) {
                    wmma::mma_sync(acc[i][j], ah[i], bh, acc[i][j]);
                    wmma::mma_sync(acc[i][j], ah[i], bl, acc[i][j]);
                    wmma::mma_sync(acc[i][j], al[i], bh, acc[i][j]);
                }
            }
        }
        __syncthreads();
    }

    float* Cs = reinterpret_cast<float*>(sm);
#pragma unroll
    for (int i = 0; i < 2; i++)
#pragma unroll
        for (int j = 0; j < 4; j++)
            wmma::store_matrix_sync(Cs + (warp_m + 16 * i) * EPI_LD + warp_n + 16 * j,
                                    acc[i][j], EPI_LD, wmma::mem_row_major);
    __syncthreads();

    if (SPLIT_OUT && ntile == 17) {
        // V block: write transposed Vt[b][d][s] split bf16 (skip qkv store)
        const int b2 = mtile >> 4;                // batch
        const int s0 = (mtile & 15) * 128;        // seq offset
#pragma unroll
        for (int it = 0; it < 32; it++) {
            int idx = tid + it * 256;             // 0..8191
            int d = idx >> 6;                     // 0..127
            int sp = idx & 63;                    // s-pair index
            float bconst = bias[2176 + d];
            float v0 = Cs[(2 * sp) * EPI_LD + d] + bconst;
            float v1 = Cs[(2 * sp + 1) * EPI_LD + d] + bconst;
            __nv_bfloat16 h0, l0, h1, l1;
            splitf(v0, h0, l0); splitf(v1, h1, l1);
            __nv_bfloat162 hp = {h0, h1}, lp = {l0, l1};
            size_t o = (size_t)(b2 * HDIM + d) * SS + s0 + 2 * sp;
            *reinterpret_cast<__nv_bfloat162*>(&Vthi[o]) = hp;
            *reinterpret_cast<__nv_bfloat162*>(&Vtlo[o]) = lp;
        }
        return;
    }

    // Q-column scale (QKV GEMM only): cols < H*HD get 1/sqrt(HD), post-bias.
    const float qs = (SPLIT_OUT && ntile < (HH * HDIM) / 128)
                     ? 0.08838834764831845f : 1.0f;

#pragma unroll
    for (int it = 0; it < 16; it++) {
        int idx = tid + it * 256;
        int row = idx >> 5;
        int c4 = (idx & 31) * 4;
        float4 v = *reinterpret_cast<const float4*>(&Cs[row * EPI_LD + c4]);
        const int col0 = ntile * 128 + c4;
        v.x += bias[col0 + 0];
        v.y += bias[col0 + 1];
        v.z += bias[col0 + 2];
        v.w += bias[col0 + 3];
        const size_t o = (size_t)(mtile * 128 + row) * N + col0;
        if (SPLIT_OUT) {
            v.x *= qs; v.y *= qs; v.z *= qs; v.w *= qs;
            __nv_bfloat16 h0, h1, h2, h3, l0, l1, l2, l3;
            splitf(v.x, h0, l0); splitf(v.y, h1, l1);
            splitf(v.z, h2, l2); splitf(v.w, h3, l3);
            __nv_bfloat162 hp0 = {h0, h1}, hp1 = {h2, h3};
            __nv_bfloat162 lp0 = {l0, l1}, lp1 = {l2, l3};
            *reinterpret_cast<__nv_bfloat162*>(&Chi[o]) = hp0;
            *reinterpret_cast<__nv_bfloat162*>(&Chi[o + 2]) = hp1;
            *reinterpret_cast<__nv_bfloat162*>(&Clo[o]) = lp0;
            *reinterpret_cast<__nv_bfloat162*>(&Clo[o + 2]) = lp1;
        } else {
            *reinterpret_cast<float4*>(&C[o]) = v;
        }
    }
}

// ---------------------------------------------------------------------------
// MQA flash attention v6 (round-11 proven, 3-term everywhere) — mma m16n8k16,
// pre-scaled Q, peeled diagonal tile, branch-free mainloop, cp.async ping-pong.
// ---------------------------------------------------------------------------
#define ALD 136
#define ATILE (128 * ALD)

__global__ __launch_bounds__(256, 1) void mqa_attn_v6(
    const __nv_bfloat16* __restrict__ qhi, const __nv_bfloat16* __restrict__ qlo,
    const __nv_bfloat16* __restrict__ vthi, const __nv_bfloat16* __restrict__ vtlo,
    __nv_bfloat16* __restrict__ ohi, __nv_bfloat16* __restrict__ olo)
{
    extern __shared__ __nv_bfloat16 smh[];
    __nv_bfloat16* Qhi = smh;
    __nv_bfloat16* Qlo = smh + ATILE;
    __nv_bfloat16* Khi = smh + 2 * ATILE;
    __nv_bfloat16* Klo = smh + 3 * ATILE;
    __nv_bfloat16* Vhi = smh + 4 * ATILE;
    __nv_bfloat16* Vlo = smh + 5 * ATILE;
    const uint32_t smb = smem_u32(smh);
    const uint32_t oQhi = 0, oQlo = ATILE * 2, oKhi = 2 * ATILE * 2,
                   oKlo = 3 * ATILE * 2, oVhi = 4 * ATILE * 2, oVlo = 5 * ATILE * 2;

    const int tid = threadIdx.x;
    const int w = tid >> 5;
    const int lane = tid & 31;
    const int g = lane >> 2;
    const int t = lane & 3;
    const int b = blockIdx.y;
    const int q0 = (gridDim.x - 1 - blockIdx.x) * 8;   // heaviest first

    const int r_lo = w * 16 + g;

    // ---- async load Q (pre-scaled by QKV epilogue) ----
#pragma unroll
    for (int it = 0; it < 8; ++it) {
        int idx = tid + it * 256;
        int row = idx >> 4;
        int ch = idx & 15;
        size_t src = (size_t)(b * SS + q0 + (row & 7)) * NQKV + (row >> 3) * HDIM + ch * 8;
        uint32_t d = (uint32_t)(row * ALD + ch * 8) * 2;
        cp_async16(smb + oQhi + d, qhi + src);
        cp_async16(smb + oQlo + d, qlo + src);
    }
    // ---- async load K(0) ----
#pragma unroll
    for (int it = 0; it < 8; ++it) {
        int idx = tid + it * 256;
        int row = idx >> 4;
        int ch = idx & 15;
        size_t src = (size_t)(b * SS + row) * NQKV + HH * HDIM + ch * 8;
        uint32_t d = (uint32_t)(row * ALD + ch * 8) * 2;
        cp_async16(smb + oKhi + d, qhi + src);
        cp_async16(smb + oKlo + d, qlo + src);
    }
    cp_commit();

    float m0 = -INFINITY, m1 = -INFINITY, l0s = 0.0f, l1s = 0.0f;
    float O[16][4];
#pragma unroll
    for (int j = 0; j < 16; j++)
#pragma unroll
        for (int c = 0; c < 4; c++) O[j][c] = 0.0f;

    const int ntiles = (q0 + 7) / 128 + 1;

    auto softmax_update = [&](float s[16][4]) {
        float mx0 = -INFINITY, mx1 = -INFINITY;
#pragma unroll
        for (int j = 0; j < 16; ++j) {
            mx0 = fmaxf(mx0, fmaxf(s[j][0], s[j][1]));
            mx1 = fmaxf(mx1, fmaxf(s[j][2], s[j][3]));
        }
        mx0 = fmaxf(mx0, __shfl_xor_sync(0xffffffffu, mx0, 1));
        mx0 = fmaxf(mx0, __shfl_xor_sync(0xffffffffu, mx0, 2));
        mx1 = fmaxf(mx1, __shfl_xor_sync(0xffffffffu, mx1, 1));
        mx1 = fmaxf(mx1, __shfl_xor_sync(0xffffffffu, mx1, 2));
        const float mn0 = fmaxf(m0, mx0), mn1 = fmaxf(m1, mx1);
        const float corr0 = __expf(m0 - mn0), corr1 = __expf(m1 - mn1);
        m0 = mn0; m1 = mn1;

        float sum0 = 0.0f, sum1 = 0.0f;
#pragma unroll
        for (int j = 0; j < 16; ++j) {
            s[j][0] = __expf(s[j][0] - mn0);
            s[j][1] = __expf(s[j][1] - mn0);
            s[j][2] = __expf(s[j][2] - mn1);
            s[j][3] = __expf(s[j][3] - mn1);
            sum0 += s[j][0] + s[j][1];
            sum1 += s[j][2] + s[j][3];
        }
        sum0 += __shfl_xor_sync(0xffffffffu, sum0, 1);
        sum0 += __shfl_xor_sync(0xffffffffu, sum0, 2);
        sum1 += __shfl_xor_sync(0xffffffffu, sum1, 1);
        sum1 += __shfl_xor_sync(0xffffffffu, sum1, 2);
        l0s = l0s * corr0 + sum0;
        l1s = l1s * corr1 + sum1;

#pragma unroll
        for (int j = 0; j < 16; ++j) {
            O[j][0] *= corr0; O[j][1] *= corr0;
            O[j][2] *= corr1; O[j][3] *= corr1;
        }
    };

    auto repack = [&](const float s[16][4], uint32_t pah[8][4], uint32_t pal[8][4]) {
#pragma unroll
        for (int ss = 0; ss < 8; ++ss) {
            __nv_bfloat16 h, l;
            float h00, q00, h01, q01, h10, q10, h11, q11;
            float h20, q20, h21, q21, h30, q30, h31, q31;
            splitf(s[2 * ss][0], h, l); h00 = __bfloat162float(h); q00 = __bfloat162float(l);
            splitf(s[2 * ss][1], h, l); h01 = __bfloat162float(h); q01 = __bfloat162float(l);
            splitf(s[2 * ss][2], h, l); h10 = __bfloat162float(h); q10 = __bfloat162float(l);
            splitf(s[2 * ss][3], h, l); h11 = __bfloat162float(h); q11 = __bfloat162float(l);
            splitf(s[2 * ss + 1][0], h, l); h20 = __bfloat162float(h); q20 = __bfloat162float(l);
            splitf(s[2 * ss + 1][1], h, l); h21 = __bfloat162float(h); q21 = __bfloat162float(l);
            splitf(s[2 * ss + 1][2], h, l); h30 = __bfloat162float(h); q30 = __bfloat162float(l);
            splitf(s[2 * ss + 1][3], h, l); h31 = __bfloat162float(h); q31 = __bfloat162float(l);
            pah[ss][0] = pack2(h00, h01); pal[ss][0] = pack2(q00, q01);
            pah[ss][1] = pack2(h10, h11); pal[ss][1] = pack2(q10, q11);
            pah[ss][2] = pack2(h20, h21); pal[ss][2] = pack2(q20, q21);
            pah[ss][3] = pack2(h30, h31); pal[ss][3] = pack2(q30, q31);
        }
    };

    auto issue_V = [&](int t0) {
#pragma unroll
        for (int it = 0; it < 8; ++it) {
            int idx = tid + it * 256;
            int row = idx >> 4;
            int ch = idx & 15;
            size_t src = (size_t)(b * HDIM + row) * SS + t0 + ch * 8;
            uint32_t d = (uint32_t)(row * ALD + ch * 8) * 2;
            cp_async16(smb + oVhi + d, vthi + src);
            cp_async16(smb + oVlo + d, vtlo + src);
        }
        cp_commit();
    };

    auto load_Qfrag = [&](int k, uint32_t ah[4], uint32_t al[4]) {
        const int d0 = 16 * k + 2 * t;
        ah[0] = *reinterpret_cast<const uint32_t*>(&Qhi[r_lo * ALD + d0]);
        ah[1] = *reinterpret_cast<const uint32_t*>(&Qhi[(r_lo + 8) * ALD + d0]);
        ah[2] = *reinterpret_cast<const uint32_t*>(&Qhi[r_lo * ALD + d0 + 8]);
        ah[3] = *reinterpret_cast<const uint32_t*>(&Qhi[(r_lo + 8) * ALD + d0 + 8]);
        al[0] = *reinterpret_cast<const uint32_t*>(&Qlo[r_lo * ALD + d0]);
        al[1] = *reinterpret_cast<const uint32_t*>(&Qlo[(r_lo + 8) * ALD + d0]);
        al[2] = *reinterpret_cast<const uint32_t*>(&Qlo[r_lo * ALD + d0 + 8]);
        al[3] = *reinterpret_cast<const uint32_t*>(&Qlo[(r_lo + 8) * ALD + d0 + 8]);
    };

    cp_wait<0>();
    __syncthreads();

    // ================= mainloop: full tiles, branch-free =================
    for (int tt = 0; tt < ntiles - 1; ++tt) {
        const int t0 = tt * 128;

        issue_V(t0);

        float s[16][4];
#pragma unroll
        for (int j = 0; j < 16; j++)
#pragma unroll
            for (int c = 0; c < 4; c++) s[j][c] = 0.0f;

#pragma unroll
        for (int k = 0; k < 8; ++k) {
            uint32_t ah[4], al[4];
            load_Qfrag(k, ah, al);
            const int d0 = 16 * k + 2 * t;
#pragma unroll
            for (int j = 0; j < 16; ++j) {
                const int kr = (8 * j + g) * ALD + d0;
                uint32_t bh0 = *reinterpret_cast<const uint32_t*>(&Khi[kr]);
                uint32_t bh1 = *reinterpret_cast<const uint32_t*>(&Khi[kr + 8]);
                uint32_t bl0 = *reinterpret_cast<const uint32_t*>(&Klo[kr]);
                uint32_t bl1 = *reinterpret_cast<const uint32_t*>(&Klo[kr + 8]);
                mma_bf16(s[j], ah, bh0, bh1);
                mma_bf16(s[j], ah, bl0, bl1);
                mma_bf16(s[j], al, bh0, bh1);
            }
        }

        cp_wait<0>();
        __syncthreads();

        softmax_update(s);

        uint32_t pah[8][4], pal[8][4];
        repack(s, pah, pal);

        // issue K(tt+1)
        {
            const int t1 = t0 + 128;
#pragma unroll
            for (int it = 0; it < 8; ++it) {
                int idx = tid + it * 256;
                int row = idx >> 4;
                int ch = idx & 15;
                size_t src = (size_t)(b * SS + t1 + row) * NQKV + HH * HDIM + ch * 8;
                uint32_t d = (uint32_t)(row * ALD + ch * 8) * 2;
                cp_async16(smb + oKhi + d, qhi + src);
                cp_async16(smb + oKlo + d, qlo + src);
            }
            cp_commit();
        }

        // PV, branch-free
#pragma unroll
        for (int ss = 0; ss < 8; ++ss) {
            const int kb = 16 * ss + 2 * t;
#pragma unroll
            for (int j2 = 0; j2 < 16; ++j2) {
                const int vr = (8 * j2 + g) * ALD + kb;
                uint32_t bh0 = *reinterpret_cast<const uint32_t*>(&Vhi[vr]);
                uint32_t bh1 = *reinterpret_cast<const uint32_t*>(&Vhi[vr + 8]);
                uint32_t bl0 = *reinterpret_cast<const uint32_t*>(&Vlo[vr]);
                uint32_t bl1 = *reinterpret_cast<const uint32_t*>(&Vlo[vr + 8]);
                mma_bf16(O[j2], pah[ss], bh0, bh1);
                mma_bf16(O[j2], pah[ss], bl0, bl1);
                mma_bf16(O[j2], pal[ss], bh0, bh1);
            }
        }

        cp_wait<0>();
        __syncthreads();
    }

    // ================= peeled diagonal tile =================
    {
        const int t0 = (ntiles - 1) * 128;
        const int nvalid = q0 + 8 - t0;
        const int njfrag = (nvalid + 7) >> 3;
        const int nsfrag = (nvalid + 15) >> 4;

        issue_V(t0);

        float s[16][4];
#pragma unroll
        for (int j = 0; j < 16; j++)
#pragma unroll
            for (int c = 0; c < 4; c++) s[j][c] = 0.0f;

#pragma unroll
        for (int k = 0; k < 8; ++k) {
            uint32_t ah[4], al[4];
            load_Qfrag(k, ah, al);
            const int d0 = 16 * k + 2 * t;
            for (int j = 0; j < njfrag; ++j) {
                const int kr = (8 * j + g) * ALD + d0;
                uint32_t bh0 = *reinterpret_cast<const uint32_t*>(&Khi[kr]);
                uint32_t bh1 = *reinterpret_cast<const uint32_t*>(&Khi[kr + 8]);
                uint32_t bl0 = *reinterpret_cast<const uint32_t*>(&Klo[kr]);
                uint32_t bl1 = *reinterpret_cast<const uint32_t*>(&Klo[kr + 8]);
                mma_bf16(s[j], ah, bh0, bh1);
                mma_bf16(s[j], ah, bl0, bl1);
                mma_bf16(s[j], al, bh0, bh1);
            }
        }

        cp_wait<0>();
        __syncthreads();

#pragma unroll
        for (int j = 0; j < 16; ++j) {
            const int col = t0 + 8 * j + 2 * t;
            if (col > q0 + g)     { s[j][0] = -1e30f; s[j][2] = -1e30f; }
            if (col + 1 > q0 + g) { s[j][1] = -1e30f; s[j][3] = -1e30f; }
        }

        softmax_update(s);

        uint32_t pah[8][4], pal[8][4];
        repack(s, pah, pal);

        for (int ss = 0; ss < nsfrag; ++ss) {
            const int kb = 16 * ss + 2 * t;
#pragma unroll
            for (int j2 = 0; j2 < 16; ++j2) {
                const int vr = (8 * j2 + g) * ALD + kb;
                uint32_t bh0 = *reinterpret_cast<const uint32_t*>(&Vhi[vr]);
                uint32_t bh1 = *reinterpret_cast<const uint32_t*>(&Vhi[vr + 8]);
                uint32_t bl0 = *reinterpret_cast<const uint32_t*>(&Vlo[vr]);
                uint32_t bl1 = *reinterpret_cast<const uint32_t*>(&Vlo[vr + 8]);
                mma_bf16(O[j2], pah[ss], bh0, bh1);
                mma_bf16(O[j2], pah[ss], bl0, bl1);
                mma_bf16(O[j2], pal[ss], bh0, bh1);
            }
        }
    }

    // ---- epilogue: normalize + split-store bf16 hi/lo ----
    const float inv0 = 1.0f / l0s, inv1 = 1.0f / l1s;
    const size_t row0 = (size_t)(b * SS + q0 + g) * DD;
    const int h_lo = 2 * w, h_hi = 2 * w + 1;
#pragma unroll
    for (int j2 = 0; j2 < 16; ++j2) {
        const int d = 8 * j2 + 2 * t;
        float v00 = O[j2][0] * inv0, v01 = O[j2][1] * inv0;
        float v10 = O[j2][2] * inv1, v11 = O[j2][3] * inv1;
        __nv_bfloat16 h0, l0, h1, l1;
        splitf(v00, h0, l0); splitf(v01, h1, l1);
        __nv_bfloat162 hp = {h0, h1}, lp = {l0, l1};
        *reinterpret_cast<__nv_bfloat162*>(&ohi[row0 + h_lo * HDIM + d]) = hp;
        *reinterpret_cast<__nv_bfloat162*>(&olo[row0 + h_lo * HDIM + d]) = lp;
        splitf(v10, h0, l0); splitf(v11, h1, l1);
        __nv_bfloat162 hp2 = {h0, h1}, lp2 = {l0, l1};
        *reinterpret_cast<__nv_bfloat162*>(&ohi[row0 + h_hi * HDIM + d]) = hp2;
        *reinterpret_cast<__nv_bfloat162*>(&olo[row0 + h_hi * HDIM + d]) = lp2;
    }
}

// ---------------------------------------------------------------------------
extern "C" void kernel_launch(void* const* d_in, const int* in_sizes, int n_in,
                              void* d_out, int out_size)
{
    const float* hidden = (const float*)d_in[0];
    const float* W_attn = (const float*)d_in[1];
    const float* b_attn = (const float*)d_in[2];
    const float* W_proj = (const float*)d_in[3];
    const float* b_proj = (const float*)d_in[4];
    float* out = (float*)d_out;

    __nv_bfloat16 *qkvhi, *qkvlo, *Xhi, *Xlo, *WaThi, *WaTlo, *WpThi, *WpTlo;
    __nv_bfloat16 *AThi, *ATlo, *Vthi, *Vtlo;
    cudaGetSymbolAddress((void**)&qkvhi, g_qkvhi);
    cudaGetSymbolAddress((void**)&qkvlo, g_qkvlo);
    cudaGetSymbolAddress((void**)&Xhi, g_Xhi);
    cudaGetSymbolAddress((void**)&Xlo, g_Xlo);
    cudaGetSymbolAddress((void**)&WaThi, g_WaThi);
    cudaGetSymbolAddress((void**)&WaTlo, g_WaTlo);
    cudaGetSymbolAddress((void**)&WpThi, g_WpThi);
    cudaGetSymbolAddress((void**)&WpTlo, g_WpTlo);
    cudaGetSymbolAddress((void**)&AThi, g_AThi);
    cudaGetSymbolAddress((void**)&ATlo, g_ATlo);
    cudaGetSymbolAddress((void**)&Vthi, g_Vthi);
    cudaGetSymbolAddress((void**)&Vtlo, g_Vtlo);

    const int attn_smem = 6 * ATILE * sizeof(__nv_bfloat16);      // 208,896 B
    const int gemm_smem = 2 * BUF_BYTES;                          // 81,920 B
    cudaFuncSetAttribute(mqa_attn_v6,
                         cudaFuncAttributeMaxDynamicSharedMemorySize, attn_smem);
    cudaFuncSetAttribute(wmma_gemm_bias<true>,
                         cudaFuncAttributeMaxDynamicSharedMemorySize, gemm_smem);
    cudaFuncSetAttribute(wmma_gemm_bias<false>,
                         cudaFuncAttributeMaxDynamicSharedMemorySize, gemm_smem);

    // 0) input splits
    split_kernel<<<MM * DD / 4096, 256>>>(hidden, Xhi, Xlo, MM * DD);
    {
        dim3 g(NQKV / 32, DD / 32), blk(32, 8);
        split_transpose_kernel<<<g, blk>>>(W_attn, WaThi, WaTlo, DD, NQKV);
    }
    {
        dim3 g(DD / 32, DD / 32), blk(32, 8);
        split_transpose_kernel<<<g, blk>>>(W_proj, WpThi, WpTlo, DD, DD);
    }

    // 1) QKV GEMM -> split bf16 output (Q pre-scaled; V written transposed)
    {
        dim3 grid(NQKV / 128, MM / 128);
        wmma_gemm_bias<true><<<grid, 256, gemm_smem>>>(
            Xhi, Xlo, WaThi, WaTlo, b_attn, nullptr, qkvhi, qkvlo,
            Vthi, Vtlo, MM, NQKV, DD);
    }

    // 2) MQA causal flash attention -> split bf16 output
    {
        dim3 grid(SS / 8, BB);
        mqa_attn_v6<<<grid, 256, attn_smem>>>(qkvhi, qkvlo, Vthi, Vtlo, AThi, ATlo);
    }

    // 3) Projection GEMM -> f32 final output
    {
        dim3 grid(DD / 128, MM / 128);
        wmma_gemm_bias<false><<<grid, 256, gemm_smem>>>(
            AThi, ATlo, WpThi, WpTlo, b_proj, out, nullptr, nullptr,
            nullptr, nullptr, MM, DD, DD);
    }
}

// round 17
// speedup vs baseline: 1.0433x; 1.0038x over previous
#include <cuda_runtime.h>
#include <cuda_bf16.h>
#include <mma.h>
#include <math.h>
#include <cstdint>

using namespace nvcuda;

// Problem constants (GPTBigCode MQA)
#define BB 2
#define SS 2048
#define DD 2048
#define HH 16
#define HDIM 128
#define NQKV (HH * HDIM + 2 * HDIM)   // 2304
#define MM (BB * SS)                  // 4096

// ---------------- scratch (device globals; no allocation allowed) ----------
__device__ __nv_bfloat16 g_qkvhi[MM * NQKV];          // QKV out split [M,2304]
__device__ __nv_bfloat16 g_qkvlo[MM * NQKV];
__device__ __nv_bfloat16 g_Xhi[MM * DD];              // hidden split [M,K]
__device__ __nv_bfloat16 g_Xlo[MM * DD];
__device__ __nv_bfloat16 g_WaThi[NQKV * DD];          // W_attn^T split [N,K]
__device__ __nv_bfloat16 g_WaTlo[NQKV * DD];
__device__ __nv_bfloat16 g_WpThi[DD * DD];            // W_proj^T split [N,K]
__device__ __nv_bfloat16 g_WpTlo[DD * DD];
__device__ __nv_bfloat16 g_AThi[MM * DD];             // attention out split [M,K]
__device__ __nv_bfloat16 g_ATlo[MM * DD];
__device__ __nv_bfloat16 g_Vthi[BB * HDIM * SS];      // V transposed [B][d][s]
__device__ __nv_bfloat16 g_Vtlo[BB * HDIM * SS];

// ---------------- helpers ---------------------------------------------------
__device__ __forceinline__ uint32_t smem_u32(const void* p) {
    uint32_t a;
    asm("{ .reg .u64 t; cvta.to.shared.u64 t, %1; cvt.u32.u64 %0, t; }" : "=r"(a) : "l"(p));
    return a;
}
__device__ __forceinline__ void cp_async16(uint32_t dst, const void* src) {
    asm volatile("cp.async.cg.shared.global [%0], [%1], 16;" :: "r"(dst), "l"(src));
}
__device__ __forceinline__ void cp_commit() {
    asm volatile("cp.async.commit_group;" ::: "memory");
}
template <int N>
__device__ __forceinline__ void cp_wait() {
    asm volatile("cp.async.wait_group %0;" :: "n"(N) : "memory");
}
__device__ __forceinline__ void mma_bf16(float* c, const uint32_t* a,
                                         uint32_t b0, uint32_t b1) {
    asm volatile("mma.sync.aligned.m16n8k16.row.col.f32.bf16.bf16.f32 "
        "{%0,%1,%2,%3}, {%4,%5,%6,%7}, {%8,%9}, {%0,%1,%2,%3};"
        : "+f"(c[0]), "+f"(c[1]), "+f"(c[2]), "+f"(c[3])
        : "r"(a[0]), "r"(a[1]), "r"(a[2]), "r"(a[3]), "r"(b0), "r"(b1));
}
__device__ __forceinline__ void splitf(float v, __nv_bfloat16& h, __nv_bfloat16& l) {
    h = __float2bfloat16(v);
    l = __float2bfloat16(v - __bfloat162float(h));
}
__device__ __forceinline__ uint32_t pack2(float a, float b) {   // a->low, b->high
    uint32_t r;
    asm("cvt.rn.bf16x2.f32 %0, %1, %2;" : "=r"(r) : "f"(b), "f"(a));
    return r;
}
// hi = bf16x2(a,b); lo = bf16x2 of residuals (identical math to splitf pairs)
__device__ __forceinline__ void split_pack(float a, float b,
                                           uint32_t& ph, uint32_t& pl) {
    ph = pack2(a, b);
    float ha = __uint_as_float(ph << 16);
    float hb = __uint_as_float(ph & 0xFFFF0000u);
    pl = pack2(a - ha, b - hb);
}
__device__ __forceinline__ float ex2(float x) {
    float r;
    asm("ex2.approx.f32 %0, %1;" : "=f"(r) : "f"(x));
    return r;
}

// ---------------------------------------------------------------------------
// split: fp32 -> (bf16 hi, bf16 lo); 4 float4 per thread for MLP=4
// ---------------------------------------------------------------------------
__global__ __launch_bounds__(256) void split_kernel(
    const float* __restrict__ X, __nv_bfloat16* __restrict__ hi,
    __nv_bfloat16* __restrict__ lo, int n)
{
    const int base = blockIdx.x * 4096 + threadIdx.x * 4;
    float4 v[4];
#pragma unroll
    for (int u = 0; u < 4; u++)
        v[u] = *reinterpret_cast<const float4*>(&X[base + u * 1024]);
#pragma unroll
    for (int u = 0; u < 4; u++) {
        const int i = base + u * 1024;
        __nv_bfloat16 h0, h1, h2, h3, l0, l1, l2, l3;
        splitf(v[u].x, h0, l0); splitf(v[u].y, h1, l1);
        splitf(v[u].z, h2, l2); splitf(v[u].w, h3, l3);
        __nv_bfloat162 hp0 = {h0, h1}, hp1 = {h2, h3}, lp0 = {l0, l1}, lp1 = {l2, l3};
        *reinterpret_cast<__nv_bfloat162*>(&hi[i]) = hp0;
        *reinterpret_cast<__nv_bfloat162*>(&hi[i + 2]) = hp1;
        *reinterpret_cast<__nv_bfloat162*>(&lo[i]) = lp0;
        *reinterpret_cast<__nv_bfloat162*>(&lo[i + 2]) = lp1;
    }
}

// ---------------------------------------------------------------------------
// split + transpose: W[K,N] fp32 -> T{hi,lo}[N,K] bf16
// ---------------------------------------------------------------------------
__global__ __launch_bounds__(256) void split_transpose_kernel(
    const float* __restrict__ W, __nv_bfloat16* __restrict__ Thi,
    __nv_bfloat16* __restrict__ Tlo, int K, int N)
{
    __shared__ float t[32][33];
    int tx = threadIdx.x, ty = threadIdx.y;
    int n0 = blockIdx.x * 32, k0 = blockIdx.y * 32;
#pragma unroll
    for (int i = 0; i < 4; i++)
        t[ty + 8 * i][tx] = W[(size_t)(k0 + ty + 8 * i) * N + n0 + tx];
    __syncthreads();
#pragma unroll
    for (int i = 0; i < 4; i++) {
        float v = t[tx][ty + 8 * i];
        __nv_bfloat16 h, l;
        splitf(v, h, l);
        size_t o = (size_t)(n0 + ty + 8 * i) * K + k0 + tx;
        Thi[o] = h;
        Tlo[o] = l;
    }
}

// ---------------------------------------------------------------------------
// wmma bf16 3-term split GEMM + bias (256 threads, warp tile 32x64, 2 CTA/SM).
// Round-11 proven mainloop. SPLIT_OUT: Q cols pre-scaled by 1/sqrt(HD)*log2(e)
// (softmax runs in base-2 domain); ntile 17 (V block) writes transposed
// Vt{hi,lo} directly.
// ---------------------------------------------------------------------------
#define BK 32
#define LDT 40
#define TILE_HB (128 * LDT)
#define TILE_BYTES (TILE_HB * 2)
#define BUF_BYTES (4 * TILE_BYTES)
#define EPI_LD 136

template <bool SPLIT_OUT>
__global__ __launch_bounds__(256, 2)
void wmma_gemm_bias(const __nv_bfloat16* __restrict__ Ahi,
                    const __nv_bfloat16* __restrict__ Alo,
                    const __nv_bfloat16* __restrict__ Bhi,
                    const __nv_bfloat16* __restrict__ Blo,
                    const float* __restrict__ bias, float* __restrict__ C,
                    __nv_bfloat16* __restrict__ Chi, __nv_bfloat16* __restrict__ Clo,
                    __nv_bfloat16* __restrict__ Vthi, __nv_bfloat16* __restrict__ Vtlo,
                    int M, int N, int K)
{
    extern __shared__ char sm[];
    const uint32_t smb = smem_u32(sm);
    const int tid = threadIdx.x;
    const int wid = tid >> 5;
    const int ntile = blockIdx.x, mtile = blockIdx.y;

    const int warp_m = (wid >> 1) * 32;
    const int warp_n = (wid & 1) * 64;

    const __nv_bfloat16* srcs[4] = {
        Ahi + (size_t)mtile * 128 * K, Alo + (size_t)mtile * 128 * K,
        Bhi + (size_t)ntile * 128 * K, Blo + (size_t)ntile * 128 * K };

    auto issue_load = [&](int b, int k0) {
        const uint32_t bufb = smb + b * BUF_BYTES;
#pragma unroll
        for (int t = 0; t < 4; t++) {
            const __nv_bfloat16* s = srcs[t];
            const uint32_t tb = bufb + t * TILE_BYTES;
#pragma unroll
            for (int it = 0; it < 2; it++) {
                int idx = tid + it * 256;
                int row = idx >> 2;
                int ch = idx & 3;
                cp_async16(tb + (row * LDT + ch * 8) * 2,
                           s + (size_t)row * K + k0 + ch * 8);
            }
        }
        cp_commit();
    };

    wmma::fragment<wmma::accumulator, 16, 16, 16, float> acc[2][4];
#pragma unroll
    for (int i = 0; i < 2; i++)
#pragma unroll
        for (int j = 0; j < 4; j++) wmma::fill_fragment(acc[i][j], 0.0f);

    const int niter = K / BK;
    issue_load(0, 0);

    for (int iter = 0; iter < niter; iter++) {
        const int buf = iter & 1;
        if (iter + 1 < niter) {
            issue_load(buf ^ 1, (iter + 1) * BK);
            cp_wait<1>();
        } else {
            cp_wait<0>();
        }
        __syncthreads();

        const __nv_bfloat16* base = reinterpret_cast<const __nv_bfloat16*>(sm + buf * BUF_BYTES);
        const __nv_bfloat16* As_hi = base;
        const __nv_bfloat16* As_lo = base + TILE_HB;
        const __nv_bfloat16* Bs_hi = base + 2 * TILE_HB;
        const __nv_bfloat16* Bs_lo = base + 3 * TILE_HB;

#pragma unroll
        for (int kk = 0; kk < BK; kk += 16) {
            wmma::fragment<wmma::matrix_a, 16, 16, 16, __nv_bfloat16, wmma::row_major> ah[2], al[2];
#pragma unroll
            for (int i = 0; i < 2; i++) {
                wmma::load_matrix_sync(ah[i], As_hi + (warp_m + 16 * i) * LDT + kk, LDT);
                wmma::load_matrix_sync(al[i], As_lo + (warp_m + 16 * i) * LDT + kk, LDT);
            }
#pragma unroll
            for (int j = 0; j < 4; j++) {
                wmma::fragment<wmma::matrix_b, 16, 16, 16, __nv_bfloat16, wmma::col_major> bh, bl;
                wmma::load_matrix_sync(bh, Bs_hi + (warp_n + 16 * j) * LDT + kk, LDT);
                wmma::load_matrix_sync(bl, Bs_lo + (warp_n + 16 * j) * LDT + kk, LDT);
#pragma unroll
                for (int i = 0; i < 2; i++) {
                    wmma::mma_sync(acc[i][j], ah[i], bh, acc[i][j]);
                    wmma::mma_sync(acc[i][j], ah[i], bl, acc[i][j]);
                    wmma::mma_sync(acc[i][j], al[i], bh, acc[i][j]);
                }
            }
        }
        __syncthreads();
    }

    float* Cs = reinterpret_cast<float*>(sm);
#pragma unroll
    for (int i = 0; i < 2; i++)
#pragma unroll
        for (int j = 0; j < 4; j++)
            wmma::store_matrix_sync(Cs + (warp_m + 16 * i) * EPI_LD + warp_n + 16 * j,
                                    acc[i][j], EPI_LD, wmma::mem_row_major);
    __syncthreads();

    if (SPLIT_OUT && ntile == 17) {
        // V block: write transposed Vt[b][d][s] split bf16 (skip qkv store)
        const int b2 = mtile >> 4;                // batch
        const int s0 = (mtile & 15) * 128;        // seq offset
#pragma unroll
        for (int it = 0; it < 32; it++) {
            int idx = tid + it * 256;             // 0..8191
            int d = idx >> 6;                     // 0..127
            int sp = idx & 63;                    // s-pair index
            float bconst = bias[2176 + d];
            float v0 = Cs[(2 * sp) * EPI_LD + d] + bconst;
            float v1 = Cs[(2 * sp + 1) * EPI_LD + d] + bconst;
            __nv_bfloat16 h0, l0, h1, l1;
            splitf(v0, h0, l0); splitf(v1, h1, l1);
            __nv_bfloat162 hp = {h0, h1}, lp = {l0, l1};
            size_t o = (size_t)(b2 * HDIM + d) * SS + s0 + 2 * sp;
            *reinterpret_cast<__nv_bfloat162*>(&Vthi[o]) = hp;
            *reinterpret_cast<__nv_bfloat162*>(&Vtlo[o]) = lp;
        }
        return;
    }

    // Q-column scale (QKV GEMM only): 1/sqrt(HD) * log2(e) for base-2 softmax.
    const float qs = (SPLIT_OUT && ntile < (HH * HDIM) / 128)
                     ? 0.127517434f : 1.0f;

#pragma unroll
    for (int it = 0; it < 16; it++) {
        int idx = tid + it * 256;
        int row = idx >> 5;
        int c4 = (idx & 31) * 4;
        float4 v = *reinterpret_cast<const float4*>(&Cs[row * EPI_LD + c4]);
        const int col0 = ntile * 128 + c4;
        v.x += bias[col0 + 0];
        v.y += bias[col0 + 1];
        v.z += bias[col0 + 2];
        v.w += bias[col0 + 3];
        const size_t o = (size_t)(mtile * 128 + row) * N + col0;
        if (SPLIT_OUT) {
            v.x *= qs; v.y *= qs; v.z *= qs; v.w *= qs;
            __nv_bfloat16 h0, h1, h2, h3, l0, l1, l2, l3;
            splitf(v.x, h0, l0); splitf(v.y, h1, l1);
            splitf(v.z, h2, l2); splitf(v.w, h3, l3);
            __nv_bfloat162 hp0 = {h0, h1}, hp1 = {h2, h3};
            __nv_bfloat162 lp0 = {l0, l1}, lp1 = {l2, l3};
            *reinterpret_cast<__nv_bfloat162*>(&Chi[o]) = hp0;
            *reinterpret_cast<__nv_bfloat162*>(&Chi[o + 2]) = hp1;
            *reinterpret_cast<__nv_bfloat162*>(&Clo[o]) = lp0;
            *reinterpret_cast<__nv_bfloat162*>(&Clo[o + 2]) = lp1;
        } else {
            *reinterpret_cast<float4*>(&C[o]) = v;
        }
    }
}

// ---------------------------------------------------------------------------
// MQA flash attention v9 — v6 structure + base-2 softmax (ex2.approx),
// pack-then-extract repack, early K(tt+1) issue.
// ---------------------------------------------------------------------------
#define ALD 136
#define ATILE (128 * ALD)

__global__ __launch_bounds__(256, 1) void mqa_attn_v9(
    const __nv_bfloat16* __restrict__ qhi, const __nv_bfloat16* __restrict__ qlo,
    const __nv_bfloat16* __restrict__ vthi, const __nv_bfloat16* __restrict__ vtlo,
    __nv_bfloat16* __restrict__ ohi, __nv_bfloat16* __restrict__ olo)
{
    extern __shared__ __nv_bfloat16 smh[];
    __nv_bfloat16* Qhi = smh;
    __nv_bfloat16* Qlo = smh + ATILE;
    __nv_bfloat16* Khi = smh + 2 * ATILE;
    __nv_bfloat16* Klo = smh + 3 * ATILE;
    __nv_bfloat16* Vhi = smh + 4 * ATILE;
    __nv_bfloat16* Vlo = smh + 5 * ATILE;
    const uint32_t smb = smem_u32(smh);
    const uint32_t oQhi = 0, oQlo = ATILE * 2, oKhi = 2 * ATILE * 2,
                   oKlo = 3 * ATILE * 2, oVhi = 4 * ATILE * 2, oVlo = 5 * ATILE * 2;

    const int tid = threadIdx.x;
    const int w = tid >> 5;
    const int lane = tid & 31;
    const int g = lane >> 2;
    const int t = lane & 3;
    const int b = blockIdx.y;
    const int q0 = (gridDim.x - 1 - blockIdx.x) * 8;   // heaviest first

    const int r_lo = w * 16 + g;

    // ---- async load Q (pre-scaled by QKV epilogue, log2 domain) ----
#pragma unroll
    for (int it = 0; it < 8; ++it) {
        int idx = tid + it * 256;
        int row = idx >> 4;
        int ch = idx & 15;
        size_t src = (size_t)(b * SS + q0 + (row & 7)) * NQKV + (row >> 3) * HDIM + ch * 8;
        uint32_t d = (uint32_t)(row * ALD + ch * 8) * 2;
        cp_async16(smb + oQhi + d, qhi + src);
        cp_async16(smb + oQlo + d, qlo + src);
    }
    // ---- async load K(0) ----
#pragma unroll
    for (int it = 0; it < 8; ++it) {
        int idx = tid + it * 256;
        int row = idx >> 4;
        int ch = idx & 15;
        size_t src = (size_t)(b * SS + row) * NQKV + HH * HDIM + ch * 8;
        uint32_t d = (uint32_t)(row * ALD + ch * 8) * 2;
        cp_async16(smb + oKhi + d, qhi + src);
        cp_async16(smb + oKlo + d, qlo + src);
    }
    cp_commit();

    float m0 = -INFINITY, m1 = -INFINITY, l0s = 0.0f, l1s = 0.0f;
    float O[16][4];
#pragma unroll
    for (int j = 0; j < 16; j++)
#pragma unroll
        for (int c = 0; c < 4; c++) O[j][c] = 0.0f;

    const int ntiles = (q0 + 7) / 128 + 1;

    auto softmax_update = [&](float s[16][4]) {
        float mx0 = -INFINITY, mx1 = -INFINITY;
#pragma unroll
        for (int j = 0; j < 16; ++j) {
            mx0 = fmaxf(mx0, fmaxf(s[j][0], s[j][1]));
            mx1 = fmaxf(mx1, fmaxf(s[j][2], s[j][3]));
        }
        mx0 = fmaxf(mx0, __shfl_xor_sync(0xffffffffu, mx0, 1));
        mx0 = fmaxf(mx0, __shfl_xor_sync(0xffffffffu, mx0, 2));
        mx1 = fmaxf(mx1, __shfl_xor_sync(0xffffffffu, mx1, 1));
        mx1 = fmaxf(mx1, __shfl_xor_sync(0xffffffffu, mx1, 2));
        const float mn0 = fmaxf(m0, mx0), mn1 = fmaxf(m1, mx1);
        const float corr0 = ex2(m0 - mn0), corr1 = ex2(m1 - mn1);
        m0 = mn0; m1 = mn1;

        float sum0 = 0.0f, sum1 = 0.0f;
#pragma unroll
        for (int j = 0; j < 16; ++j) {
            s[j][0] = ex2(s[j][0] - mn0);
            s[j][1] = ex2(s[j][1] - mn0);
            s[j][2] = ex2(s[j][2] - mn1);
            s[j][3] = ex2(s[j][3] - mn1);
            sum0 += s[j][0] + s[j][1];
            sum1 += s[j][2] + s[j][3];
        }
        sum0 += __shfl_xor_sync(0xffffffffu, sum0, 1);
        sum0 += __shfl_xor_sync(0xffffffffu, sum0, 2);
        sum1 += __shfl_xor_sync(0xffffffffu, sum1, 1);
        sum1 += __shfl_xor_sync(0xffffffffu, sum1, 2);
        l0s = l0s * corr0 + sum0;
        l1s = l1s * corr1 + sum1;

#pragma unroll
        for (int j = 0; j < 16; ++j) {
            O[j][0] *= corr0; O[j][1] *= corr0;
            O[j][2] *= corr1; O[j][3] *= corr1;
        }
    };

    auto repack = [&](const float s[16][4], uint32_t pah[8][4], uint32_t pal[8][4]) {
#pragma unroll
        for (int ss = 0; ss < 8; ++ss) {
            split_pack(s[2 * ss][0],     s[2 * ss][1],     pah[ss][0], pal[ss][0]);
            split_pack(s[2 * ss][2],     s[2 * ss][3],     pah[ss][1], pal[ss][1]);
            split_pack(s[2 * ss + 1][0], s[2 * ss + 1][1], pah[ss][2], pal[ss][2]);
            split_pack(s[2 * ss + 1][2], s[2 * ss + 1][3], pah[ss][3], pal[ss][3]);
        }
    };

    auto issue_V = [&](int t0) {
#pragma unroll
        for (int it = 0; it < 8; ++it) {
            int idx = tid + it * 256;
            int row = idx >> 4;
            int ch = idx & 15;
            size_t src = (size_t)(b * HDIM + row) * SS + t0 + ch * 8;
            uint32_t d = (uint32_t)(row * ALD + ch * 8) * 2;
            cp_async16(smb + oVhi + d, vthi + src);
            cp_async16(smb + oVlo + d, vtlo + src);
        }
        cp_commit();
    };

    auto load_Qfrag = [&](int k, uint32_t ah[4], uint32_t al[4]) {
        const int d0 = 16 * k + 2 * t;
        ah[0] = *reinterpret_cast<const uint32_t*>(&Qhi[r_lo * ALD + d0]);
        ah[1] = *reinterpret_cast<const uint32_t*>(&Qhi[(r_lo + 8) * ALD + d0]);
        ah[2] = *reinterpret_cast<const uint32_t*>(&Qhi[r_lo * ALD + d0 + 8]);
        ah[3] = *reinterpret_cast<const uint32_t*>(&Qhi[(r_lo + 8) * ALD + d0 + 8]);
        al[0] = *reinterpret_cast<const uint32_t*>(&Qlo[r_lo * ALD + d0]);
        al[1] = *reinterpret_cast<const uint32_t*>(&Qlo[(r_lo + 8) * ALD + d0]);
        al[2] = *reinterpret_cast<const uint32_t*>(&Qlo[r_lo * ALD + d0 + 8]);
        al[3] = *reinterpret_cast<const uint32_t*>(&Qlo[(r_lo + 8) * ALD + d0 + 8]);
    };

    cp_wait<0>();
    __syncthreads();

    // ================= mainloop: full tiles, branch-free =================
    for (int tt = 0; tt < ntiles - 1; ++tt) {
        const int t0 = tt * 128;

        issue_V(t0);

        float s[16][4];
#pragma unroll
        for (int j = 0; j < 16; j++)
#pragma unroll
            for (int c = 0; c < 4; c++) s[j][c] = 0.0f;

#pragma unroll
        for (int k = 0; k < 8; ++k) {
            uint32_t ah[4], al[4];
            load_Qfrag(k, ah, al);
            const int d0 = 16 * k + 2 * t;
#pragma unroll
            for (int j = 0; j < 16; ++j) {
                const int kr = (8 * j + g) * ALD + d0;
                uint32_t bh0 = *reinterpret_cast<const uint32_t*>(&Khi[kr]);
                uint32_t bh1 = *reinterpret_cast<const uint32_t*>(&Khi[kr + 8]);
                uint32_t bl0 = *reinterpret_cast<const uint32_t*>(&Klo[kr]);
                uint32_t bl1 = *reinterpret_cast<const uint32_t*>(&Klo[kr + 8]);
                mma_bf16(s[j], ah, bh0, bh1);
                mma_bf16(s[j], ah, bl0, bl1);
                mma_bf16(s[j], al, bh0, bh1);
            }
        }

        cp_wait<0>();        // V(tt) arrived
        __syncthreads();     // all warps past QK -> K buffers free

        // issue K(tt+1) early: overlaps softmax + repack + PV
        {
            const int t1 = t0 + 128;
#pragma unroll
            for (int it = 0; it < 8; ++it) {
                int idx = tid + it * 256;
                int row = idx >> 4;
                int ch = idx & 15;
                size_t src = (size_t)(b * SS + t1 + row) * NQKV + HH * HDIM + ch * 8;
                uint32_t d = (uint32_t)(row * ALD + ch * 8) * 2;
                cp_async16(smb + oKhi + d, qhi + src);
                cp_async16(smb + oKlo + d, qlo + src);
            }
            cp_commit();
        }

        softmax_update(s);

        uint32_t pah[8][4], pal[8][4];
        repack(s, pah, pal);

        // PV, branch-free
#pragma unroll
        for (int ss = 0; ss < 8; ++ss) {
            const int kb = 16 * ss + 2 * t;
#pragma unroll
            for (int j2 = 0; j2 < 16; ++j2) {
                const int vr = (8 * j2 + g) * ALD + kb;
                uint32_t bh0 = *reinterpret_cast<const uint32_t*>(&Vhi[vr]);
                uint32_t bh1 = *reinterpret_cast<const uint32_t*>(&Vhi[vr + 8]);
                uint32_t bl0 = *reinterpret_cast<const uint32_t*>(&Vlo[vr]);
                uint32_t bl1 = *reinterpret_cast<const uint32_t*>(&Vlo[vr + 8]);
                mma_bf16(O[j2], pah[ss], bh0, bh1);
                mma_bf16(O[j2], pah[ss], bl0, bl1);
                mma_bf16(O[j2], pal[ss], bh0, bh1);
            }
        }

        cp_wait<0>();
        __syncthreads();
    }

    // ================= peeled diagonal tile =================
    {
        const int t0 = (ntiles - 1) * 128;
        const int nvalid = q0 + 8 - t0;
        const int njfrag = (nvalid + 7) >> 3;
        const int nsfrag = (nvalid + 15) >> 4;

        issue_V(t0);

        float s[16][4];
#pragma unroll
        for (int j = 0; j < 16; j++)
#pragma unroll
            for (int c = 0; c < 4; c++) s[j][c] = 0.0f;

#pragma unroll
        for (int k = 0; k < 8; ++k) {
            uint32_t ah[4], al[4];
            load_Qfrag(k, ah, al);
            const int d0 = 16 * k + 2 * t;
            for (int j = 0; j < njfrag; ++j) {
                const int kr = (8 * j + g) * ALD + d0;
                uint32_t bh0 = *reinterpret_cast<const uint32_t*>(&Khi[kr]);
                uint32_t bh1 = *reinterpret_cast<const uint32_t*>(&Khi[kr + 8]);
                uint32_t bl0 = *reinterpret_cast<const uint32_t*>(&Klo[kr]);
                uint32_t bl1 = *reinterpret_cast<const uint32_t*>(&Klo[kr + 8]);
                mma_bf16(s[j], ah, bh0, bh1);
                mma_bf16(s[j], ah, bl0, bl1);
                mma_bf16(s[j], al, bh0, bh1);
            }
        }

        cp_wait<0>();
        __syncthreads();

#pragma unroll
        for (int j = 0; j < 16; ++j) {
            const int col = t0 + 8 * j + 2 * t;
            if (col > q0 + g)     { s[j][0] = -1e30f; s[j][2] = -1e30f; }
            if (col + 1 > q0 + g) { s[j][1] = -1e30f; s[j][3] = -1e30f; }
        }

        softmax_update(s);

        uint32_t pah[8][4], pal[8][4];
        repack(s, pah, pal);

        for (int ss = 0; ss < nsfrag; ++ss) {
            const int kb = 16 * ss + 2 * t;
#pragma unroll
            for (int j2 = 0; j2 < 16; ++j2) {
                const int vr = (8 * j2 + g) * ALD + kb;
                uint32_t bh0 = *reinterpret_cast<const uint32_t*>(&Vhi[vr]);
                uint32_t bh1 = *reinterpret_cast<const uint32_t*>(&Vhi[vr + 8]);
                uint32_t bl0 = *reinterpret_cast<const uint32_t*>(&Vlo[vr]);
                uint32_t bl1 = *reinterpret_cast<const uint32_t*>(&Vlo[vr + 8]);
                mma_bf16(O[j2], pah[ss], bh0, bh1);
                mma_bf16(O[j2], pah[ss], bl0, bl1);
                mma_bf16(O[j2], pal[ss], bh0, bh1);
            }
        }
    }

    // ---- epilogue: normalize + split-store bf16 hi/lo ----
    const float inv0 = 1.0f / l0s, inv1 = 1.0f / l1s;
    const size_t row0 = (size_t)(b * SS + q0 + g) * DD;
    const int h_lo = 2 * w, h_hi = 2 * w + 1;
#pragma unroll
    for (int j2 = 0; j2 < 16; ++j2) {
        const int d = 8 * j2 + 2 * t;
        uint32_t ph, pl;
        split_pack(O[j2][0] * inv0, O[j2][1] * inv0, ph, pl);
        *reinterpret_cast<uint32_t*>(&ohi[row0 + h_lo * HDIM + d]) = ph;
        *reinterpret_cast<uint32_t*>(&olo[row0 + h_lo * HDIM + d]) = pl;
        split_pack(O[j2][2] * inv1, O[j2][3] * inv1, ph, pl);
        *reinterpret_cast<uint32_t*>(&ohi[row0 + h_hi * HDIM + d]) = ph;
        *reinterpret_cast<uint32_t*>(&olo[row0 + h_hi * HDIM + d]) = pl;
    }
}

// ---------------------------------------------------------------------------
extern "C" void kernel_launch(void* const* d_in, const int* in_sizes, int n_in,
                              void* d_out, int out_size)
{
    const float* hidden = (const float*)d_in[0];
    const float* W_attn = (const float*)d_in[1];
    const float* b_attn = (const float*)d_in[2];
    const float* W_proj = (const float*)d_in[3];
    const float* b_proj = (const float*)d_in[4];
    float* out = (float*)d_out;

    __nv_bfloat16 *qkvhi, *qkvlo, *Xhi, *Xlo, *WaThi, *WaTlo, *WpThi, *WpTlo;
    __nv_bfloat16 *AThi, *ATlo, *Vthi, *Vtlo;
    cudaGetSymbolAddress((void**)&qkvhi, g_qkvhi);
    cudaGetSymbolAddress((void**)&qkvlo, g_qkvlo);
    cudaGetSymbolAddress((void**)&Xhi, g_Xhi);
    cudaGetSymbolAddress((void**)&Xlo, g_Xlo);
    cudaGetSymbolAddress((void**)&WaThi, g_WaThi);
    cudaGetSymbolAddress((void**)&WaTlo, g_WaTlo);
    cudaGetSymbolAddress((void**)&WpThi, g_WpThi);
    cudaGetSymbolAddress((void**)&WpTlo, g_WpTlo);
    cudaGetSymbolAddress((void**)&AThi, g_AThi);
    cudaGetSymbolAddress((void**)&ATlo, g_ATlo);
    cudaGetSymbolAddress((void**)&Vthi, g_Vthi);
    cudaGetSymbolAddress((void**)&Vtlo, g_Vtlo);

    const int attn_smem = 6 * ATILE * sizeof(__nv_bfloat16);      // 208,896 B
    const int gemm_smem = 2 * BUF_BYTES;                          // 81,920 B
    cudaFuncSetAttribute(mqa_attn_v9,
                         cudaFuncAttributeMaxDynamicSharedMemorySize, attn_smem);
    cudaFuncSetAttribute(wmma_gemm_bias<true>,
                         cudaFuncAttributeMaxDynamicSharedMemorySize, gemm_smem);
    cudaFuncSetAttribute(wmma_gemm_bias<false>,
                         cudaFuncAttributeMaxDynamicSharedMemorySize, gemm_smem);

    // 0) input splits
    split_kernel<<<MM * DD / 4096, 256>>>(hidden, Xhi, Xlo, MM * DD);
    {
        dim3 g(NQKV / 32, DD / 32), blk(32, 8);
        split_transpose_kernel<<<g, blk>>>(W_attn, WaThi, WaTlo, DD, NQKV);
    }
    {
        dim3 g(DD / 32, DD / 32), blk(32, 8);
        split_transpose_kernel<<<g, blk>>>(W_proj, WpThi, WpTlo, DD, DD);
    }

    // 1) QKV GEMM -> split bf16 output (Q pre-scaled incl. log2e; V transposed)
    {
        dim3 grid(NQKV / 128, MM / 128);
        wmma_gemm_bias<true><<<grid, 256, gemm_smem>>>(
            Xhi, Xlo, WaThi, WaTlo, b_attn, nullptr, qkvhi, qkvlo,
            Vthi, Vtlo, MM, NQKV, DD);
    }

    // 2) MQA causal flash attention -> split bf16 output
    {
        dim3 grid(SS / 8, BB);
        mqa_attn_v9<<<grid, 256, attn_smem>>>(qkvhi, qkvlo, Vthi, Vtlo, AThi, ATlo);
    }

    // 3) Projection GEMM -> f32 final output
    {
        dim3 grid(DD / 128, MM / 128);
        wmma_gemm_bias<false><<<grid, 256, gemm_smem>>>(
            AThi, ATlo, WpThi, WpTlo, b_proj, out, nullptr, nullptr,
            nullptr, nullptr, MM, DD, DD);
    }
}